// round 15
// baseline (speedup 1.0000x reference)
#include <cuda_runtime.h>
#include <cstdint>

// Problem constants (fixed by setup_inputs)
#define BB   64
#define DD   128
#define TT   2048
#define KK   1024
#define NN   (BB*TT)          // 131072 tokens

// Output layout (float32, concatenated flattened tuple):
// out[B,D,T] (16777216) | loss_commit (1) | loss_vq (1) | idx (131072) | new_embeddings (131072)
#define OFF_LC  16777216
#define OFF_VQ  16777217
#define OFF_IDX 16777218
#define OFF_NE  (16777218 + 131072)

// Scratch (no allocations allowed -> device globals)
__device__ float g_counts[KK];
__device__ float g_dw[KK*DD];
__device__ float g_cs[KK];
__device__ float g_en[KK];      // |e_k|^2 (full, fp32 sequential like ref row-sum)
__device__ float g_loss;

// ---------------------------------------------------------------------------
// Kernel 0: zero scratch + precompute |e_k|^2
// ---------------------------------------------------------------------------
__global__ void vq_init(const float* __restrict__ emb)
{
    int i = blockIdx.x * 256 + threadIdx.x;
    if (i < KK*DD) g_dw[i] = 0.0f;
    if (i < KK) {
        g_counts[i] = 0.0f;
        const float* er = emb + i * DD;
        float s = 0.0f;
        #pragma unroll 8
        for (int d = 0; d < DD; ++d) s = fmaf(er[d], er[d], s);
        g_en[i] = s;
    }
    if (i == 0) g_loss = 0.0f;
}

// ---------------------------------------------------------------------------
// Kernel 1: main fused kernel.
// Block = 128 tokens. For each of 8 code-chunks (128 codes), accumulate exact
// fp32 dot(x,e) with packed fma.rn.f32x2 (token pairs). Epilogue per candidate
// EMULATES the reference's rounding:
//     dist = fp32( fp32(|x|^2 + |e|^2) - 2*dot )
// (the subtraction happens at magnitude ~128 -> ulp ~1e-5, so near-ties
// collapse into the same fp32 cell exactly like the reference) and argmin
// scans k ascending with strict '<' => first-occurrence tie-break, matching
// jnp.argmin. Then: idx, counts atomics, loss partial, dw scatter
// (red.v4.f32), quantized tile write (coalesced via smem staging).
// ---------------------------------------------------------------------------
__global__ __launch_bounds__(256, 1)
void vq_main(const float* __restrict__ x, const float* __restrict__ emb,
             float* __restrict__ out)
{
    extern __shared__ float smem[];
    float* xs    = smem;                 // [128][128] : xs[d][n]
    float* es    = xs + 128*128;         // [128][129] : es[k_local][d] (pad->conflict-free)
    float* en_s  = es + 128*129;         // [128]  |e|^2 for chunk
    float* xnorm = en_s + 128;           // [128]  |x|^2 per token
    float* sm_bs = xnorm + 128;          // [128]  best dist per token
    int*   sm_bk = (int*)(sm_bs + 128);  // [128]  best k per token
    float* redbuf = (float*)(sm_bk + 128); // [8]

    const int tid = threadIdx.x;
    const int n0  = blockIdx.x * 128;            // global token base (b*T + t order)
    const int b   = n0 >> 11;                    // T = 2048
    const int t0  = n0 & 2047;
    const size_t xbase = (size_t)b * (DD*TT) + (size_t)t0;   // x[b, d, t] = x[xbase + d*T + i]

    // ---- load x tile [128 d][128 tokens], coalesced ----
    {
        const int dd = tid >> 5, lane = tid & 31;
        #pragma unroll
        for (int r = 0; r < 16; ++r) {
            int d = dd + r * 8;
            float4 v = *(const float4*)(x + xbase + (size_t)d * TT + lane * 4);
            *(float4*)(xs + d * 128 + lane * 4) = v;
        }
    }
    __syncthreads();

    // ---- per-token |x|^2 (the 'a' term of the reference dist) ----
    if (tid < 128) {
        float s = 0.0f;
        #pragma unroll 8
        for (int d = 0; d < 128; ++d) { float v = xs[d * 128 + tid]; s = fmaf(v, v, s); }
        xnorm[tid] = s;
    }
    __syncthreads();

    const int tx = tid & 15;   // code lane (codes tx + 16j within chunk)
    const int ty = tid >> 4;   // token group (tokens ty*8 .. ty*8+7)

    // hoist this thread's 8 token norms into registers
    float axn[8];
    #pragma unroll
    for (int t = 0; t < 8; ++t) axn[t] = xnorm[ty * 8 + t];

    float bs[8];
    int   bk[8];
    #pragma unroll
    for (int t = 0; t < 8; ++t) { bs[t] = 3.4e38f; bk[t] = 0; }

    for (int kc = 0; kc < 8; ++kc) {
        __syncthreads();   // protect es from previous chunk readers
        // load embedding chunk (natural [k][d], row pad 129 -> conflict-free)
        {
            const int kl = tid >> 1;
            const int d0 = (tid & 1) * 64;
            const float* src = emb + (size_t)(kc * 128 + kl) * 128 + d0;
            float* dst = es + kl * 129 + d0;
            #pragma unroll
            for (int d = 0; d < 64; d += 4) {
                float4 v = *(const float4*)(src + d);
                dst[d + 0] = v.x; dst[d + 1] = v.y; dst[d + 2] = v.z; dst[d + 3] = v.w;
            }
            if (tid < 128) en_s[tid] = g_en[kc * 128 + tid];
        }
        __syncthreads();

        // accumulators: acc[j*4+i] holds tokens {2i,2i+1} x code (tx+16j), packed f32x2
        unsigned long long acc[32];
        #pragma unroll
        for (int i = 0; i < 32; ++i) acc[i] = 0ULL;

        const float* xcol = xs + ty * 8;
        const float* ecol = es + tx * 129;

        #pragma unroll 2
        for (int d = 0; d < 128; ++d) {
            ulonglong2 A0 = *(const ulonglong2*)(xcol + d * 128);
            ulonglong2 A1 = *(const ulonglong2*)(xcol + d * 128 + 4);
            unsigned long long a0 = A0.x, a1 = A0.y, a2 = A1.x, a3 = A1.y;
            #pragma unroll
            for (int j = 0; j < 8; ++j) {
                float bv = ecol[j * (16 * 129) + d];
                unsigned long long bb;
                asm("mov.b64 %0, {%1, %1};" : "=l"(bb) : "r"(__float_as_uint(bv)));
                asm("fma.rn.f32x2 %0, %1, %2, %0;" : "+l"(acc[j*4+0]) : "l"(a0), "l"(bb));
                asm("fma.rn.f32x2 %0, %1, %2, %0;" : "+l"(acc[j*4+1]) : "l"(a1), "l"(bb));
                asm("fma.rn.f32x2 %0, %1, %2, %0;" : "+l"(acc[j*4+2]) : "l"(a2), "l"(bb));
                asm("fma.rn.f32x2 %0, %1, %2, %0;" : "+l"(acc[j*4+3]) : "l"(a3), "l"(bb));
            }
        }

        // fold into reference-rounded distance and update running argmin.
        // k is strictly ascending per thread across j and chunks -> strict '<'
        // keeps the lowest k on exact (rounded) ties, matching jnp.argmin.
        #pragma unroll
        for (int j = 0; j < 8; ++j) {
            const int kl = tx + 16 * j;
            const float en = en_s[kl];
            const int kg = kc * 128 + kl;
            #pragma unroll
            for (int i = 0; i < 4; ++i) {
                unsigned lo, hi;
                asm("mov.b64 {%0, %1}, %2;" : "=r"(lo), "=r"(hi) : "l"(acc[j*4+i]));
                // dist = ( (|x|^2 + |e|^2) - 2*dot ), each op rounded fp32
                float d0v = (axn[2*i]   + en) - 2.0f * __uint_as_float(lo);
                float d1v = (axn[2*i+1] + en) - 2.0f * __uint_as_float(hi);
                if (d0v < bs[2*i])   { bs[2*i]   = d0v; bk[2*i]   = kg; }
                if (d1v < bs[2*i+1]) { bs[2*i+1] = d1v; bk[2*i+1] = kg; }
            }
        }
    }

    // ---- reduce argmin across the 16 code-lanes (stays inside 16-lane halves) ----
    #pragma unroll
    for (int off = 8; off >= 1; off >>= 1) {
        #pragma unroll
        for (int t = 0; t < 8; ++t) {
            float os = __shfl_xor_sync(0xffffffffu, bs[t], off);
            int   ok = __shfl_xor_sync(0xffffffffu, bk[t], off);
            if (os < bs[t] || (os == bs[t] && ok < bk[t])) { bs[t] = os; bk[t] = ok; }
        }
    }
    if (tx == 0) {
        #pragma unroll
        for (int t = 0; t < 8; ++t) { sm_bs[ty*8 + t] = bs[t]; sm_bk[ty*8 + t] = bk[t]; }
    }
    __syncthreads();

    // ---- per-token: idx, counts, loss partial ----
    if (tid < 128) {
        const int k = sm_bk[tid];
        out[OFF_IDX + n0 + tid] = (float)k;
        atomicAdd(&g_counts[k], 1.0f);
        float dist = sm_bs[tid];            // == sum_d (x-e)^2 up to fp32 rounding
        #pragma unroll
        for (int off = 16; off >= 1; off >>= 1)
            dist += __shfl_xor_sync(0xffffffffu, dist, off);
        if ((tid & 31) == 0) redbuf[tid >> 5] = dist;
    }
    __syncthreads();
    if (tid == 0)
        atomicAdd(&g_loss, redbuf[0] + redbuf[1] + redbuf[2] + redbuf[3]);

    // ---- dw scatter: dw[k] += x_n, vectorized red.v4.f32 ----
    {
        const int n  = tid >> 1;
        const int d0 = (tid & 1) * 64;
        const int k  = sm_bk[n];
        float* dst = g_dw + k * 128;
        #pragma unroll
        for (int d = d0; d < d0 + 64; d += 4) {
            float v0 = xs[(d + 0) * 128 + n];
            float v1 = xs[(d + 1) * 128 + n];
            float v2 = xs[(d + 2) * 128 + n];
            float v3 = xs[(d + 3) * 128 + n];
            asm volatile("red.global.add.v4.f32 [%0], {%1,%2,%3,%4};"
                         :: "l"(dst + d), "f"(v0), "f"(v1), "f"(v2), "f"(v3) : "memory");
        }
    }

    // ---- quantized tile: gather e rows into smem (reuse es), then coalesced out ----
    float* qs = es;   // qs[d][n], 128*128 fits in es region
    {
        const int n  = tid >> 1;
        const int d0 = (tid & 1) * 64;
        const float* er = emb + (size_t)sm_bk[n] * 128;
        #pragma unroll
        for (int d = d0; d < d0 + 64; d += 4) {
            float4 v = *(const float4*)(er + d);
            qs[(d + 0) * 128 + n] = v.x;
            qs[(d + 1) * 128 + n] = v.y;
            qs[(d + 2) * 128 + n] = v.z;
            qs[(d + 3) * 128 + n] = v.w;
        }
    }
    __syncthreads();
    {
        const int dd = tid >> 5, lane = tid & 31;
        #pragma unroll
        for (int r = 0; r < 16; ++r) {
            int d = dd + r * 8;
            float4 v = *(const float4*)(qs + d * 128 + lane * 4);
            *(float4*)(out + xbase + (size_t)d * TT + lane * 4) = v;
        }
    }
}

// ---------------------------------------------------------------------------
// Kernel 2: cluster-size smoothing + losses (single block, K threads)
// ---------------------------------------------------------------------------
__global__ void vq_finalize(const float* __restrict__ ema_cs, float* __restrict__ out)
{
    __shared__ float sm[KK];
    const int k = threadIdx.x;
    const float c1 = (float)(1.0 - 0.99);   // matches python double->f32
    const float c2 = c1;                    // 1 - 0.99**1
    float cnt = g_counts[k];
    float ec  = ema_cs[k];
    float avg = (ec - (ec - cnt) * c1) / c2;
    sm[k] = avg;
    __syncthreads();
    for (int off = 512; off >= 1; off >>= 1) {
        if (k < off) sm[k] += sm[k + off];
        __syncthreads();
    }
    const float n = sm[0];
    float cs = (avg + 1e-5f) / (n + (float)(1024 * 1e-5)) * n;
    g_cs[k] = cs;
    if (k == 0) {
        float mean = g_loss * (1.0f / 16777216.0f);
        out[OFF_LC] = 0.25f * mean;   // COMMIT_COST
        out[OFF_VQ] = mean;           // VQ_COST
    }
}

// ---------------------------------------------------------------------------
// Kernel 3: new_embeddings = avg_dw / cs
// ---------------------------------------------------------------------------
__global__ void vq_newemb(const float* __restrict__ ema_dw, float* __restrict__ out)
{
    const int e = blockIdx.x * 256 + threadIdx.x;
    const float c1 = (float)(1.0 - 0.99);
    float dw = g_dw[e];
    float ed = ema_dw[e];
    float avg = (ed - (ed - dw) * c1) / c1;
    out[OFF_NE + e] = avg / g_cs[e >> 7];
}

// ---------------------------------------------------------------------------
extern "C" void kernel_launch(void* const* d_in, const int* in_sizes, int n_in,
                              void* d_out, int out_size)
{
    const float* x      = (const float*)d_in[0];   // [64,128,2048]
    const float* emb    = (const float*)d_in[1];   // [1024,128]
    const float* ema_dw = (const float*)d_in[2];   // [1024,128] (zeros)
    const float* ema_cs = (const float*)d_in[3];   // [1024]     (zeros)
    float* out = (float*)d_out;

    const size_t smem_bytes = (size_t)(128*128 + 128*129 + 128 + 128 + 128 + 128 + 8) * sizeof(float);
    cudaFuncSetAttribute(vq_main, cudaFuncAttributeMaxDynamicSharedMemorySize, (int)smem_bytes);

    vq_init<<<512, 256>>>(emb);
    vq_main<<<NN / 128, 256, smem_bytes>>>(x, emb, out);
    vq_finalize<<<1, KK>>>(ema_cs, out);
    vq_newemb<<<(KK * DD) / 256, 256>>>(ema_dw, out);
}